// round 3
// baseline (speedup 1.0000x reference)
#include <cuda_runtime.h>
#include <cstdint>

// Problem constants
#define S   8192
#define Dm  2048
#define E   64
#define CAP 128   // ceil(S/E * 1.0)

// ---------------- device scratch (no allocations allowed) ----------------
__device__ int   g_expert[S];
__device__ float g_gate[S];
__device__ int   g_rank[S];             // rank within 128-token chunk
__device__ int   g_chunkHist[64 * 64];  // [chunk][expert]
__device__ int   g_chunkBase[64 * 64];  // exclusive prefix over chunks
__device__ float g_partSum[256 * 64];   // per-block gate column sums

// ---------------------------------------------------------------------------
// Kernel 1: logits = x @ wg^T. 32 tokens x 64 experts per block, 128 threads,
// 4x4 register tile (16 FFMA per 2 LDS.128) -> fma-pipe bound.
// Then softmax, argmax (first-max), gate-at-argmax, per-block column sums.
// ---------------------------------------------------------------------------
__global__ __launch_bounds__(128, 4) void gate_kernel(const float* __restrict__ x,
                                                      const float* __restrict__ wg) {
    __shared__ __align__(16) float xs[16][36];  // [k][token] row=144B, xs[kk][ty*4] 16B-aligned
    __shared__ __align__(16) float ws[16][68];  // [k][expert] row=272B, ws[kk][tx*4] 16B-aligned
    __shared__ float colv[8][64];

    const int tid = threadIdx.x;
    const int ty  = tid >> 4;      // 0..7  -> token quad (4 tokens)
    const int tx  = tid & 15;      // 0..15 -> expert quad (4 experts)
    const int sb  = blockIdx.x * 32;

    float acc[4][4];
#pragma unroll
    for (int i = 0; i < 4; i++)
#pragma unroll
        for (int j = 0; j < 4; j++) acc[i][j] = 0.0f;

    // global-load assignments
    const int txl = tid >> 2;          // token 0..31 (x tile), float4 over k
    const int kqx = (tid & 3) * 4;     // k offset for x
    const int el  = tid >> 1;          // expert 0..63 (wg tile)
    const int kqw = (tid & 1) * 8;     // k offset for wg (two float4)

    const float* xrow = x  + (size_t)(sb + txl) * Dm + kqx;
    const float* wrow = wg + (size_t)el * Dm + kqw;

    float4 xv  = *(const float4*)(xrow);
    float4 wv0 = *(const float4*)(wrow);
    float4 wv1 = *(const float4*)(wrow + 4);

    for (int k0 = 0; k0 < Dm; k0 += 16) {
        xs[kqx    ][txl] = xv.x;
        xs[kqx + 1][txl] = xv.y;
        xs[kqx + 2][txl] = xv.z;
        xs[kqx + 3][txl] = xv.w;
        ws[kqw    ][el] = wv0.x;
        ws[kqw + 1][el] = wv0.y;
        ws[kqw + 2][el] = wv0.z;
        ws[kqw + 3][el] = wv0.w;
        ws[kqw + 4][el] = wv1.x;
        ws[kqw + 5][el] = wv1.y;
        ws[kqw + 6][el] = wv1.z;
        ws[kqw + 7][el] = wv1.w;
        __syncthreads();

        if (k0 + 16 < Dm) {  // prefetch next tile while computing
            xv  = *(const float4*)(xrow + k0 + 16);
            wv0 = *(const float4*)(wrow + k0 + 16);
            wv1 = *(const float4*)(wrow + k0 + 20);
        }

#pragma unroll
        for (int kk = 0; kk < 16; kk++) {
            const float4 a = *(const float4*)&xs[kk][ty * 4];
            const float4 b = *(const float4*)&ws[kk][tx * 4];
            acc[0][0] += a.x * b.x;  acc[0][1] += a.x * b.y;
            acc[0][2] += a.x * b.z;  acc[0][3] += a.x * b.w;
            acc[1][0] += a.y * b.x;  acc[1][1] += a.y * b.y;
            acc[1][2] += a.y * b.z;  acc[1][3] += a.y * b.w;
            acc[2][0] += a.z * b.x;  acc[2][1] += a.z * b.y;
            acc[2][2] += a.z * b.z;  acc[2][3] += a.z * b.w;
            acc[3][0] += a.w * b.x;  acc[3][1] += a.w * b.y;
            acc[3][2] += a.w * b.z;  acc[3][3] += a.w * b.w;
        }
        __syncthreads();
    }

    // softmax + argmax per token (16 lanes per token group; width-16 shuffles)
    const unsigned FULL = 0xffffffffu;
    float cadd[4] = {0.0f, 0.0f, 0.0f, 0.0f};

#pragma unroll
    for (int i = 0; i < 4; i++) {
        // max over 64 experts
        float m = fmaxf(fmaxf(acc[i][0], acc[i][1]), fmaxf(acc[i][2], acc[i][3]));
#pragma unroll
        for (int d = 8; d >= 1; d >>= 1)
            m = fmaxf(m, __shfl_xor_sync(FULL, m, d, 16));

        float ev0 = __expf(acc[i][0] - m);
        float ev1 = __expf(acc[i][1] - m);
        float ev2 = __expf(acc[i][2] - m);
        float ev3 = __expf(acc[i][3] - m);
        float ssum = ev0 + ev1 + ev2 + ev3;
#pragma unroll
        for (int d = 8; d >= 1; d >>= 1)
            ssum += __shfl_xor_sync(FULL, ssum, d, 16);
        const float rs = 1.0f / ssum;

        cadd[0] += ev0 * rs;  cadd[1] += ev1 * rs;
        cadd[2] += ev2 * rs;  cadd[3] += ev3 * rs;

        // argmax (first occurrence on ties)
        float bv = acc[i][0]; int bidx = tx * 4;
#pragma unroll
        for (int j = 1; j < 4; j++)
            if (acc[i][j] > bv) { bv = acc[i][j]; bidx = tx * 4 + j; }
#pragma unroll
        for (int d = 8; d >= 1; d >>= 1) {
            float ov = __shfl_xor_sync(FULL, bv, d, 16);
            int   oi = __shfl_xor_sync(FULL, bidx, d, 16);
            if (ov > bv || (ov == bv && oi < bidx)) { bv = ov; bidx = oi; }
        }
        if (tx == 0) {
            const int s = sb + ty * 4 + i;
            g_expert[s] = bidx;
            g_gate[s]   = rs;   // gate at argmax = exp(0)/sum = 1/sum
        }
    }

    // deterministic per-block column sums
#pragma unroll
    for (int j = 0; j < 4; j++) colv[ty][tx * 4 + j] = cadd[j];
    __syncthreads();
    if (tid < 64) {
        float sum = 0.0f;
#pragma unroll
        for (int r = 0; r < 8; r++) sum += colv[r][tid];
        g_partSum[blockIdx.x * 64 + tid] = sum;
    }
}

// ---------------------------------------------------------------------------
// Kernel 2: per-chunk (128 tokens) expert histograms + within-chunk ranks.
// ---------------------------------------------------------------------------
__global__ __launch_bounds__(128) void rank_kernel() {
    __shared__ int whist[4][64];
    const int tid = threadIdx.x;
    const int s   = blockIdx.x * 128 + tid;
    const int e   = g_expert[s];

    ((int*)whist)[tid]       = 0;
    ((int*)whist)[tid + 128] = 0;
    __syncthreads();

    const unsigned mm = __match_any_sync(0xffffffffu, e);
    const int lane = tid & 31;
    const int w    = tid >> 5;
    const int rw   = __popc(mm & ((1u << lane) - 1u));
    if ((int)(__ffs(mm) - 1) == lane) whist[w][e] = __popc(mm);
    __syncthreads();

    int before = 0;
    for (int p = 0; p < w; p++) before += whist[p][e];
    g_rank[s] = rw + before;

    if (tid < 64)
        g_chunkHist[blockIdx.x * 64 + tid] =
            whist[0][tid] + whist[1][tid] + whist[2][tid] + whist[3][tid];
}

// ---------------------------------------------------------------------------
// Kernel 3: exclusive scan of chunk hist per expert + l_aux.
// ---------------------------------------------------------------------------
__global__ __launch_bounds__(64) void scan_kernel(float* __restrict__ out, int has_laux) {
    const int e = threadIdx.x;
    int run = 0;
    for (int b = 0; b < 64; b++) {
        const int h = g_chunkHist[b * 64 + e];
        g_chunkBase[b * 64 + e] = run;
        run += h;
    }
    float gs = 0.0f;
    for (int p = 0; p < 256; p++) gs += g_partSum[p * 64 + e];

    float contrib = gs * (float)run;
#pragma unroll
    for (int d = 16; d >= 1; d >>= 1)
        contrib += __shfl_xor_sync(0xffffffffu, contrib, d);

    __shared__ float part[2];
    if ((threadIdx.x & 31) == 0) part[threadIdx.x >> 5] = contrib;
    __syncthreads();
    if (threadIdx.x == 0 && has_laux)
        out[0] = ((float)E / ((float)S * (float)S)) * (part[0] + part[1]);
}

// ---------------------------------------------------------------------------
// Kernel 4: scatter combine_weights + dispatch_mask (only kept tokens).
// ---------------------------------------------------------------------------
__global__ __launch_bounds__(256) void scatter_kernel(float* __restrict__ out,
                                                      long combine_base, int has_mask) {
    const int s = blockIdx.x * 256 + threadIdx.x;
    const int e = g_expert[s];
    const int loc = g_chunkBase[(s >> 7) * 64 + e] + g_rank[s];
    if (loc < CAP) {
        const long idx = combine_base + ((long)s * E + e) * CAP + loc;
        out[idx] = g_gate[s];
        if (has_mask) out[idx + (long)S * E * CAP] = 1.0f;
    }
}

// ---------------------------------------------------------------------------
extern "C" void kernel_launch(void* const* d_in, const int* in_sizes, int n_in,
                              void* d_out, int out_size) {
    const float* x  = (const float*)d_in[0];
    const float* wg = (const float*)d_in[1];
    float* out = (float*)d_out;

    const long SEC = (long)S * E * CAP;                 // 67,108,864
    const int has_mask = ((long)out_size >= 2 * SEC);
    const long cb = (long)out_size - (has_mask ? 2 : 1) * SEC;  // 1 if l_aux packed, else 0
    const int has_laux = (cb > 0);

    // Side stream + events for graph-forked zero-fill (created once, pre-capture:
    // the harness runs kernel_launch for correctness before capturing).
    static cudaStream_t s2 = nullptr;
    static cudaEvent_t evFork = nullptr, evJoin = nullptr;
    if (s2 == nullptr) {
        cudaStreamCreateWithFlags(&s2, cudaStreamNonBlocking);
        cudaEventCreateWithFlags(&evFork, cudaEventDisableTiming);
        cudaEventCreateWithFlags(&evJoin, cudaEventDisableTiming);
    }

    // Fork: zero-fill the 537MB output on the side stream, overlapped with the
    // GEMM/softmax work on the main (capture) stream.
    cudaEventRecord(evFork, 0);
    cudaStreamWaitEvent(s2, evFork, 0);
    cudaMemsetAsync(d_out, 0, (size_t)out_size * sizeof(float), s2);
    cudaEventRecord(evJoin, s2);

    gate_kernel<<<S / 32, 128>>>(x, wg);
    rank_kernel<<<S / 128, 128>>>();

    // Join: scan writes out[0] and scatter writes into the zeroed buffer.
    cudaStreamWaitEvent(0, evJoin, 0);
    scan_kernel<<<1, 64>>>(out, has_laux);
    scatter_kernel<<<S / 256, 256>>>(out, cb, has_mask);
}

// round 6
// speedup vs baseline: 1.3996x; 1.3996x over previous
#include <cuda_runtime.h>
#include <cstdint>

// Problem constants
#define S   8192
#define Dm  2048
#define E   64
#define CAP 128   // ceil(S/E * 1.0)

// ---------------- device scratch (no allocations allowed) ----------------
__device__ int   g_expert[S];
__device__ float g_gate[S];
__device__ int   g_rank[S];             // rank within 128-token chunk
__device__ int   g_chunkHist[64 * 64];  // [chunk][expert]
__device__ int   g_chunkBase[64 * 64];  // exclusive prefix over chunks
__device__ float g_partSum[256 * 64];   // per-block gate column sums

// packed fp32x2 FMA: d = a*b + d  (SASS FFMA2, only reachable via PTX)
#define FMA2(d, a, b) \
    asm("fma.rn.f32x2 %0, %1, %2, %0;" : "+l"(d) : "l"(a), "l"(b))
#define UNPACK2(lo, hi, v) \
    asm("mov.b64 {%0, %1}, %2;" : "=f"(lo), "=f"(hi) : "l"(v))

// ---------------------------------------------------------------------------
// Kernel 1: logits = x @ wg^T (32 tokens x 64 experts per block, FFMA2 packed
// math: per k-step 3 LDS + 4 FFMA2 = 16 FMAs), then softmax, argmax
// (first-max semantics), gate-at-argmax, per-block gate column sums.
// NO store traffic interleaved here — R2/R3 proved the giant zero-fill
// poisons this latency-sensitive tile loop when co-running.
// ---------------------------------------------------------------------------
__global__ __launch_bounds__(256, 4) void gate_kernel(const float* __restrict__ x,
                                                      const float* __restrict__ wg) {
    __shared__ __align__(16) float2 xs2[16][32];  // [k][token], value duplicated (v,v)
    __shared__ __align__(16) float  ws [16][68];  // [k][expert], row = 272B
    __shared__ float colv[16][64];

    const int tid = threadIdx.x;
    const int ty  = tid >> 4;      // 0..15 -> token pair
    const int tx  = tid & 15;      // 0..15 -> expert quad
    const int sb  = blockIdx.x * 32;

    unsigned long long acc00 = 0ull, acc01 = 0ull, acc10 = 0ull, acc11 = 0ull;

    // load assignments
    const int txl = tid >> 3;          // token 0..31 (x tile)
    const int kq2 = (tid & 7) * 2;     // k offset for x (float2)
    const int el  = tid >> 2;          // expert 0..63 (wg tile)
    const int kq4 = (tid & 3) * 4;     // k offset for wg (float4)

    const float* xrow = x  + (size_t)(sb + txl) * Dm + kq2;
    const float* wrow = wg + (size_t)el * Dm + kq4;

    float2 xv = *(const float2*)(xrow);
    float4 wv = *(const float4*)(wrow);

    for (int k0 = 0; k0 < Dm; k0 += 16) {
        xs2[kq2    ][txl] = make_float2(xv.x, xv.x);
        xs2[kq2 + 1][txl] = make_float2(xv.y, xv.y);
        ws[kq4][el]     = wv.x;
        ws[kq4 + 1][el] = wv.y;
        ws[kq4 + 2][el] = wv.z;
        ws[kq4 + 3][el] = wv.w;
        __syncthreads();

        if (k0 + 16 < Dm) {  // prefetch next tile while computing
            xv = *(const float2*)(xrow + k0 + 16);
            wv = *(const float4*)(wrow + k0 + 16);
        }

#pragma unroll
        for (int kk = 0; kk < 16; kk++) {
            const unsigned long long a0 = *(const unsigned long long*)&xs2[kk][ty * 2];
            const unsigned long long a1 = *(const unsigned long long*)&xs2[kk][ty * 2 + 1];
            const ulonglong2 b = *(const ulonglong2*)&ws[kk][tx * 4];
            FMA2(acc00, a0, b.x);  FMA2(acc01, a0, b.y);
            FMA2(acc10, a1, b.x);  FMA2(acc11, a1, b.y);
        }
        __syncthreads();
    }

    // unpack accumulators: acc[i][j] = token (ty*2+i), expert (tx*4+j)
    float acc[2][4];
    UNPACK2(acc[0][0], acc[0][1], acc00);
    UNPACK2(acc[0][2], acc[0][3], acc01);
    UNPACK2(acc[1][0], acc[1][1], acc10);
    UNPACK2(acc[1][2], acc[1][3], acc11);

    // softmax + argmax per token (16 lanes per token group; width-16 shuffles)
    const unsigned FULL = 0xffffffffu;
    float cadd[4] = {0.0f, 0.0f, 0.0f, 0.0f};

#pragma unroll
    for (int i = 0; i < 2; i++) {
        float m = fmaxf(fmaxf(acc[i][0], acc[i][1]), fmaxf(acc[i][2], acc[i][3]));
#pragma unroll
        for (int d = 8; d >= 1; d >>= 1)
            m = fmaxf(m, __shfl_xor_sync(FULL, m, d, 16));

        float ev0 = __expf(acc[i][0] - m);
        float ev1 = __expf(acc[i][1] - m);
        float ev2 = __expf(acc[i][2] - m);
        float ev3 = __expf(acc[i][3] - m);
        float ssum = ev0 + ev1 + ev2 + ev3;
#pragma unroll
        for (int d = 8; d >= 1; d >>= 1)
            ssum += __shfl_xor_sync(FULL, ssum, d, 16);
        const float rs = 1.0f / ssum;

        cadd[0] += ev0 * rs;  cadd[1] += ev1 * rs;
        cadd[2] += ev2 * rs;  cadd[3] += ev3 * rs;

        // argmax (first occurrence on ties)
        float bv = acc[i][0]; int bidx = tx * 4;
#pragma unroll
        for (int j = 1; j < 4; j++)
            if (acc[i][j] > bv) { bv = acc[i][j]; bidx = tx * 4 + j; }
#pragma unroll
        for (int d = 8; d >= 1; d >>= 1) {
            float ov = __shfl_xor_sync(FULL, bv, d, 16);
            int   oi = __shfl_xor_sync(FULL, bidx, d, 16);
            if (ov > bv || (ov == bv && oi < bidx)) { bv = ov; bidx = oi; }
        }
        if (tx == 0) {
            const int s = sb + ty * 2 + i;
            g_expert[s] = bidx;
            g_gate[s]   = rs;   // gate at argmax = exp(0)/sum = 1/sum
        }
    }

    // deterministic per-block column sums
#pragma unroll
    for (int j = 0; j < 4; j++) colv[ty][tx * 4 + j] = cadd[j];
    __syncthreads();
    if (tid < 64) {
        float sum = 0.0f;
#pragma unroll
        for (int r = 0; r < 16; r++) sum += colv[r][tid];
        g_partSum[blockIdx.x * 64 + tid] = sum;
    }
}

// ---------------------------------------------------------------------------
// Kernel 2: per-chunk (128 tokens) expert histograms + within-chunk ranks.
// ---------------------------------------------------------------------------
__global__ __launch_bounds__(128) void rank_kernel() {
    __shared__ int whist[4][64];
    const int tid = threadIdx.x;
    const int s   = blockIdx.x * 128 + tid;
    const int e   = g_expert[s];

    ((int*)whist)[tid]       = 0;
    ((int*)whist)[tid + 128] = 0;
    __syncthreads();

    const unsigned mm = __match_any_sync(0xffffffffu, e);
    const int lane = tid & 31;
    const int w    = tid >> 5;
    const int rw   = __popc(mm & ((1u << lane) - 1u));
    if ((int)(__ffs(mm) - 1) == lane) whist[w][e] = __popc(mm);
    __syncthreads();

    int before = 0;
    for (int p = 0; p < w; p++) before += whist[p][e];
    g_rank[s] = rw + before;

    if (tid < 64)
        g_chunkHist[blockIdx.x * 64 + tid] =
            whist[0][tid] + whist[1][tid] + whist[2][tid] + whist[3][tid];
}

// ---------------------------------------------------------------------------
// Kernel 3: exclusive scan of chunk hist per expert + l_aux.
// ---------------------------------------------------------------------------
__global__ __launch_bounds__(64) void scan_kernel(float* __restrict__ out, int has_laux) {
    const int e = threadIdx.x;
    int run = 0;
    for (int b = 0; b < 64; b++) {
        const int h = g_chunkHist[b * 64 + e];
        g_chunkBase[b * 64 + e] = run;
        run += h;
    }
    float gs = 0.0f;
    for (int p = 0; p < 256; p++) gs += g_partSum[p * 64 + e];

    float contrib = gs * (float)run;
#pragma unroll
    for (int d = 16; d >= 1; d >>= 1)
        contrib += __shfl_xor_sync(0xffffffffu, contrib, d);

    __shared__ float part[2];
    if ((threadIdx.x & 31) == 0) part[threadIdx.x >> 5] = contrib;
    __syncthreads();
    if (threadIdx.x == 0 && has_laux)
        out[0] = ((float)E / ((float)S * (float)S)) * (part[0] + part[1]);
}

// ---------------------------------------------------------------------------
// Kernel 4: scatter combine_weights + dispatch_mask (only kept tokens).
// ---------------------------------------------------------------------------
__global__ __launch_bounds__(256) void scatter_kernel(float* __restrict__ out,
                                                      long combine_base, int has_mask) {
    const int s = blockIdx.x * 256 + threadIdx.x;
    const int e = g_expert[s];
    const int loc = g_chunkBase[(s >> 7) * 64 + e] + g_rank[s];
    if (loc < CAP) {
        const long idx = combine_base + ((long)s * E + e) * CAP + loc;
        out[idx] = g_gate[s];
        if (has_mask) out[idx + (long)S * E * CAP] = 1.0f;
    }
}

// ---------------------------------------------------------------------------
extern "C" void kernel_launch(void* const* d_in, const int* in_sizes, int n_in,
                              void* d_out, int out_size) {
    const float* x  = (const float*)d_in[0];
    const float* wg = (const float*)d_in[1];
    float* out = (float*)d_out;

    const long SEC = (long)S * E * CAP;                 // 67,108,864
    const int has_mask = ((long)out_size >= 2 * SEC);
    const long cb = (long)out_size - (has_mask ? 2 : 1) * SEC;  // 1 if l_aux packed, else 0
    const int has_laux = (cb > 0);

    // zero-fill entire output, serial (R2/R3 showed co-running it with the
    // GEMM inflates the GEMM far more than the overlap saves)
    cudaMemsetAsync(d_out, 0, (size_t)out_size * sizeof(float), 0);

    gate_kernel<<<S / 32, 256>>>(x, wg);
    rank_kernel<<<S / 128, 128>>>();
    scan_kernel<<<1, 64>>>(out, has_laux);
    scatter_kernel<<<S / 256, 256>>>(out, cb, has_mask);
}

// round 8
// speedup vs baseline: 1.9550x; 1.3969x over previous
#include <cuda_runtime.h>
#include <cstdint>

// Problem constants
#define S   8192
#define Dm  2048
#define E   64
#define CAP 128   // ceil(S/E * 1.0)

#define GATE_BLOCKS (S / 64)   // 128 blocks, one per SM (<=148), no stragglers

// ---------------- device scratch (no allocations allowed) ----------------
__device__ int   g_expert[S];
__device__ float g_gate[S];
__device__ int   g_rank[S];             // rank within 128-token chunk
__device__ int   g_chunkHist[64 * 64];  // [chunk][expert]
__device__ int   g_chunkBase[64 * 64];  // exclusive prefix over chunks
__device__ float g_partSum[GATE_BLOCKS * 64];  // per-block gate column sums

// ---------------------------------------------------------------------------
// Kernel 1: logits = x @ wg^T. 64 tokens x 64 experts per 256-thread block,
// 4x4 register tile: per k-step 2x LDS.128 + 16 scalar FFMA (dense issue mix,
// ~1024-cycle compute window per k-tile -> highly latency tolerant).
// Grid = 128 blocks -> exactly <=1 block/SM, no straggler imbalance.
// Then softmax, argmax (first-max semantics), gate-at-argmax, column sums.
// ---------------------------------------------------------------------------
__global__ __launch_bounds__(256, 1) void gate_kernel(const float* __restrict__ x,
                                                      const float* __restrict__ wg) {
    __shared__ __align__(16) float xs[16][68];  // [k][token],  row=272B, ty*4 16B-aligned
    __shared__ __align__(16) float ws[16][68];  // [k][expert], row=272B, tx*4 16B-aligned
    __shared__ float colv[16][64];

    const int tid = threadIdx.x;
    const int ty  = tid >> 4;      // 0..15 -> token quad (4 tokens)
    const int tx  = tid & 15;      // 0..15 -> expert quad (4 experts)
    const int sb  = blockIdx.x * 64;

    float acc[4][4];
#pragma unroll
    for (int i = 0; i < 4; i++)
#pragma unroll
        for (int j = 0; j < 4; j++) acc[i][j] = 0.0f;

    // global-load assignments: one float4 of x and one of wg per thread per tile
    const int txl = tid >> 2;          // token  0..63 (x tile)
    const int el  = tid >> 2;          // expert 0..63 (wg tile)
    const int kq  = (tid & 3) * 4;     // k offset (float4)

    const float* xrow = x  + (size_t)(sb + txl) * Dm + kq;
    const float* wrow = wg + (size_t)el * Dm + kq;

    float4 xv = *(const float4*)(xrow);
    float4 wv = *(const float4*)(wrow);

    for (int k0 = 0; k0 < Dm; k0 += 16) {
        xs[kq    ][txl] = xv.x;
        xs[kq + 1][txl] = xv.y;
        xs[kq + 2][txl] = xv.z;
        xs[kq + 3][txl] = xv.w;
        ws[kq    ][el] = wv.x;
        ws[kq + 1][el] = wv.y;
        ws[kq + 2][el] = wv.z;
        ws[kq + 3][el] = wv.w;
        __syncthreads();

        if (k0 + 16 < Dm) {  // prefetch next tile while computing
            xv = *(const float4*)(xrow + k0 + 16);
            wv = *(const float4*)(wrow + k0 + 16);
        }

#pragma unroll
        for (int kk = 0; kk < 16; kk++) {
            const float4 a = *(const float4*)&xs[kk][ty * 4];
            const float4 b = *(const float4*)&ws[kk][tx * 4];
            acc[0][0] += a.x * b.x;  acc[0][1] += a.x * b.y;
            acc[0][2] += a.x * b.z;  acc[0][3] += a.x * b.w;
            acc[1][0] += a.y * b.x;  acc[1][1] += a.y * b.y;
            acc[1][2] += a.y * b.z;  acc[1][3] += a.y * b.w;
            acc[2][0] += a.z * b.x;  acc[2][1] += a.z * b.y;
            acc[2][2] += a.z * b.z;  acc[2][3] += a.z * b.w;
            acc[3][0] += a.w * b.x;  acc[3][1] += a.w * b.y;
            acc[3][2] += a.w * b.z;  acc[3][3] += a.w * b.w;
        }
        __syncthreads();
    }

    // softmax + argmax per token (16 lanes per token group; width-16 shuffles)
    const unsigned FULL = 0xffffffffu;
    float cadd[4] = {0.0f, 0.0f, 0.0f, 0.0f};

#pragma unroll
    for (int i = 0; i < 4; i++) {
        // max over 64 experts
        float m = fmaxf(fmaxf(acc[i][0], acc[i][1]), fmaxf(acc[i][2], acc[i][3]));
#pragma unroll
        for (int d = 8; d >= 1; d >>= 1)
            m = fmaxf(m, __shfl_xor_sync(FULL, m, d, 16));

        float ev0 = __expf(acc[i][0] - m);
        float ev1 = __expf(acc[i][1] - m);
        float ev2 = __expf(acc[i][2] - m);
        float ev3 = __expf(acc[i][3] - m);
        float ssum = ev0 + ev1 + ev2 + ev3;
#pragma unroll
        for (int d = 8; d >= 1; d >>= 1)
            ssum += __shfl_xor_sync(FULL, ssum, d, 16);
        const float rs = 1.0f / ssum;

        cadd[0] += ev0 * rs;  cadd[1] += ev1 * rs;
        cadd[2] += ev2 * rs;  cadd[3] += ev3 * rs;

        // argmax (first occurrence on ties)
        float bv = acc[i][0]; int bidx = tx * 4;
#pragma unroll
        for (int j = 1; j < 4; j++)
            if (acc[i][j] > bv) { bv = acc[i][j]; bidx = tx * 4 + j; }
#pragma unroll
        for (int d = 8; d >= 1; d >>= 1) {
            float ov = __shfl_xor_sync(FULL, bv, d, 16);
            int   oi = __shfl_xor_sync(FULL, bidx, d, 16);
            if (ov > bv || (ov == bv && oi < bidx)) { bv = ov; bidx = oi; }
        }
        if (tx == 0) {
            const int s = sb + ty * 4 + i;
            g_expert[s] = bidx;
            g_gate[s]   = rs;   // gate at argmax = exp(0)/sum = 1/sum
        }
    }

    // deterministic per-block column sums
#pragma unroll
    for (int j = 0; j < 4; j++) colv[ty][tx * 4 + j] = cadd[j];
    __syncthreads();
    if (tid < 64) {
        float sum = 0.0f;
#pragma unroll
        for (int r = 0; r < 16; r++) sum += colv[r][tid];
        g_partSum[blockIdx.x * 64 + tid] = sum;
    }
}

// ---------------------------------------------------------------------------
// Kernel 2: per-chunk (128 tokens) expert histograms + within-chunk ranks.
// ---------------------------------------------------------------------------
__global__ __launch_bounds__(128) void rank_kernel() {
    __shared__ int whist[4][64];
    const int tid = threadIdx.x;
    const int s   = blockIdx.x * 128 + tid;
    const int e   = g_expert[s];

    ((int*)whist)[tid]       = 0;
    ((int*)whist)[tid + 128] = 0;
    __syncthreads();

    const unsigned mm = __match_any_sync(0xffffffffu, e);
    const int lane = tid & 31;
    const int w    = tid >> 5;
    const int rw   = __popc(mm & ((1u << lane) - 1u));
    if ((int)(__ffs(mm) - 1) == lane) whist[w][e] = __popc(mm);
    __syncthreads();

    int before = 0;
    for (int p = 0; p < w; p++) before += whist[p][e];
    g_rank[s] = rw + before;

    if (tid < 64)
        g_chunkHist[blockIdx.x * 64 + tid] =
            whist[0][tid] + whist[1][tid] + whist[2][tid] + whist[3][tid];
}

// ---------------------------------------------------------------------------
// Kernel 3: exclusive scan of chunk hist per expert + l_aux.
// ---------------------------------------------------------------------------
__global__ __launch_bounds__(64) void scan_kernel(float* __restrict__ out, int has_laux) {
    const int e = threadIdx.x;
    int run = 0;
    for (int b = 0; b < 64; b++) {
        const int h = g_chunkHist[b * 64 + e];
        g_chunkBase[b * 64 + e] = run;
        run += h;
    }
    float gs = 0.0f;
    for (int p = 0; p < GATE_BLOCKS; p++) gs += g_partSum[p * 64 + e];

    float contrib = gs * (float)run;
#pragma unroll
    for (int d = 16; d >= 1; d >>= 1)
        contrib += __shfl_xor_sync(0xffffffffu, contrib, d);

    __shared__ float part[2];
    if ((threadIdx.x & 31) == 0) part[threadIdx.x >> 5] = contrib;
    __syncthreads();
    if (threadIdx.x == 0 && has_laux)
        out[0] = ((float)E / ((float)S * (float)S)) * (part[0] + part[1]);
}

// ---------------------------------------------------------------------------
// Kernel 4: scatter combine_weights + dispatch_mask (only kept tokens).
// ---------------------------------------------------------------------------
__global__ __launch_bounds__(256) void scatter_kernel(float* __restrict__ out,
                                                      long combine_base, int has_mask) {
    const int s = blockIdx.x * 256 + threadIdx.x;
    const int e = g_expert[s];
    const int loc = g_chunkBase[(s >> 7) * 64 + e] + g_rank[s];
    if (loc < CAP) {
        const long idx = combine_base + ((long)s * E + e) * CAP + loc;
        out[idx] = g_gate[s];
        if (has_mask) out[idx + (long)S * E * CAP] = 1.0f;
    }
}

// ---------------------------------------------------------------------------
extern "C" void kernel_launch(void* const* d_in, const int* in_sizes, int n_in,
                              void* d_out, int out_size) {
    const float* x  = (const float*)d_in[0];
    const float* wg = (const float*)d_in[1];
    float* out = (float*)d_out;

    const long SEC = (long)S * E * CAP;                 // 67,108,864
    const int has_mask = ((long)out_size >= 2 * SEC);
    const long cb = (long)out_size - (has_mask ? 2 : 1) * SEC;  // 1 if l_aux packed, else 0
    const int has_laux = (cb > 0);

    // zero-fill entire output, serial (R2/R3 showed co-running it with the
    // GEMM inflates the GEMM far more than the overlap saves)
    cudaMemsetAsync(d_out, 0, (size_t)out_size * sizeof(float), 0);

    gate_kernel<<<GATE_BLOCKS, 256>>>(x, wg);
    rank_kernel<<<S / 128, 128>>>();
    scan_kernel<<<1, 64>>>(out, has_laux);
    scatter_kernel<<<S / 256, 256>>>(out, cb, has_mask);
}